// round 15
// baseline (speedup 1.0000x reference)
#include <cuda_runtime.h>
#include <cuda_bf16.h>
#include <math.h>
#include <stdint.h>

#define BB 4096
#define DD 1024
#define HH 16384
#define TOPK 32
#define CAND 96
#define ROWS2 (2*BB)

// ---------------- device scratch (allocation-free) ----------------
__device__ float          g_Wn  [(size_t)HH * DD];     // normalized encoder fp32 (exact-rounded)
__device__ __nv_bfloat16  g_Wn_h[(size_t)HH * DD];
__device__ float          g_En  [(size_t)ROWS2 * DD];  // normalized embeddings fp32
__device__ __nv_bfloat16  g_En_h[(size_t)ROWS2 * DD];
__device__ __nv_bfloat16  g_cos_h[(size_t)ROWS2 * HH]; // approx cos (bf16, candidates only)
__device__ float          g_WdT [2ULL * HH * DD];      // transposed decoders [H,D]
__device__ int            g_cand[(size_t)ROWS2 * CAND];
__device__ float          g_tvals[(size_t)ROWS2 * TOPK];
__device__ int            g_tidx [(size_t)ROWS2 * TOPK];

// ---------------- exact normalize: fp64 norm, single fp32 rounding ----------------
__global__ __launch_bounds__(128) void norm_exact_kernel(const float* __restrict__ in, int which)
{
    const int tid = threadIdx.x;
    const int wid = tid >> 5, lane = tid & 31;
    const size_t row = blockIdx.x;

    float* out32;
    __nv_bfloat16* outh;
    if (which == 0) { out32 = g_Wn; outh = g_Wn_h; }
    else {
        out32 = g_En  + (size_t)(which - 1) * BB * DD;
        outh  = g_En_h + (size_t)(which - 1) * BB * DD;
    }

    const float4* ir = (const float4*)(in + row * DD);
    float4 xa = ir[2 * tid];
    float4 xb = ir[2 * tid + 1];

    double s = 0.0;
    s += (double)xa.x * xa.x; s += (double)xa.y * xa.y;
    s += (double)xa.z * xa.z; s += (double)xa.w * xa.w;
    s += (double)xb.x * xb.x; s += (double)xb.y * xb.y;
    s += (double)xb.z * xb.z; s += (double)xb.w * xb.w;

    #pragma unroll
    for (int off = 16; off; off >>= 1)
        s += __shfl_down_sync(0xffffffffu, s, off);

    __shared__ double swarp[4];
    __shared__ double srinv;
    if (lane == 0) swarp[wid] = s;
    __syncthreads();
    if (tid == 0) {
        double tot = swarp[0] + swarp[1] + swarp[2] + swarp[3];
        double n = sqrt(tot);
        if (n < 1e-12) n = 1e-12;
        srinv = 1.0 / n;
    }
    __syncthreads();
    const double r = srinv;

    float4 oa, ob;
    oa.x = (float)((double)xa.x * r); oa.y = (float)((double)xa.y * r);
    oa.z = (float)((double)xa.z * r); oa.w = (float)((double)xa.w * r);
    ob.x = (float)((double)xb.x * r); ob.y = (float)((double)xb.y * r);
    ob.z = (float)((double)xb.z * r); ob.w = (float)((double)xb.w * r);
    ((float4*)(out32 + row * DD))[2 * tid]     = oa;
    ((float4*)(out32 + row * DD))[2 * tid + 1] = ob;
    __nv_bfloat162* oh = (__nv_bfloat162*)(outh + row * DD);
    oh[4 * tid + 0] = __float22bfloat162_rn(make_float2(oa.x, oa.y));
    oh[4 * tid + 1] = __float22bfloat162_rn(make_float2(oa.z, oa.w));
    oh[4 * tid + 2] = __float22bfloat162_rn(make_float2(ob.x, ob.y));
    oh[4 * tid + 3] = __float22bfloat162_rn(make_float2(ob.z, ob.w));
}

// ---------------- decoder transpose [D,H] -> [H,D] ----------------
__global__ __launch_bounds__(256) void transpose_kernel(const float* __restrict__ vdw,
                                                        const float* __restrict__ tdw)
{
    __shared__ float tile[32][33];
    const int m = blockIdx.z;
    const float* in = m ? tdw : vdw;
    float* outp = g_WdT + (size_t)m * HH * DD;
    const int h0 = blockIdx.x * 32;
    const int d0 = blockIdx.y * 32;
    const int tx = threadIdx.x, ty = threadIdx.y;

    #pragma unroll
    for (int r = ty; r < 32; r += 8)
        tile[r][tx] = in[(size_t)(d0 + r) * HH + h0 + tx];
    __syncthreads();
    #pragma unroll
    for (int r = ty; r < 32; r += 8)
        outp[(size_t)(h0 + r) * DD + d0 + tx] = tile[tx][r];
}

// ---------------- bf16 mma.sync GEMM: approx cos (candidate generation only) -----
#define TBM 128
#define TBN 128
#define TBK 32
#define TSTR 40

__global__ __launch_bounds__(256) void gemm_kernel()
{
    __shared__ __nv_bfloat16 As[TBM * TSTR];
    __shared__ __nv_bfloat16 Bs[TBN * TSTR];

    const int tid = threadIdx.x;
    const int wid = tid >> 5, lane = tid & 31;
    const int g = lane >> 2, tg = lane & 3;
    const int warp_m = (wid & 3) * 32;
    const int warp_n = (wid >> 2) * 64;
    const int bm = blockIdx.y * TBM;
    const int bn = blockIdx.x * TBN;

    const __nv_bfloat16* __restrict__ gA = g_En_h + (size_t)bm * DD;
    const __nv_bfloat16* __restrict__ gB = g_Wn_h + (size_t)bn * DD;

    float acc[2][8][4];
    #pragma unroll
    for (int mi = 0; mi < 2; mi++)
        #pragma unroll
        for (int nj = 0; nj < 8; nj++)
            #pragma unroll
            for (int q = 0; q < 4; q++) acc[mi][nj][q] = 0.0f;

    const int lr = tid >> 2;
    const int lc = (tid & 3) << 3;

    uint4 pa[2], pb[2];
    #pragma unroll
    for (int i = 0; i < 2; i++) {
        int r = lr + (i << 6);
        pa[i] = *(const uint4*)(gA + (size_t)r * DD + lc);
        pb[i] = *(const uint4*)(gB + (size_t)r * DD + lc);
    }
    #pragma unroll
    for (int i = 0; i < 2; i++) {
        int r = lr + (i << 6);
        *(uint4*)(As + r * TSTR + lc) = pa[i];
        *(uint4*)(Bs + r * TSTR + lc) = pb[i];
    }
    __syncthreads();

    for (int k0 = 0; k0 < DD; k0 += TBK) {
        const bool has_next = (k0 + TBK) < DD;
        if (has_next) {
            #pragma unroll
            for (int i = 0; i < 2; i++) {
                int r = lr + (i << 6);
                pa[i] = *(const uint4*)(gA + (size_t)r * DD + k0 + TBK + lc);
                pb[i] = *(const uint4*)(gB + (size_t)r * DD + k0 + TBK + lc);
            }
        }

        #pragma unroll
        for (int ks = 0; ks < 2; ks++) {
            const int kb = ks * 16;
            uint32_t af[2][4], bf[8][2];
            #pragma unroll
            for (int mi = 0; mi < 2; mi++) {
                int r0 = warp_m + mi * 16 + g;
                af[mi][0] = *(const uint32_t*)(As + r0 * TSTR + kb + tg * 2);
                af[mi][1] = *(const uint32_t*)(As + (r0 + 8) * TSTR + kb + tg * 2);
                af[mi][2] = *(const uint32_t*)(As + r0 * TSTR + kb + tg * 2 + 8);
                af[mi][3] = *(const uint32_t*)(As + (r0 + 8) * TSTR + kb + tg * 2 + 8);
            }
            #pragma unroll
            for (int nj = 0; nj < 8; nj++) {
                int c0 = warp_n + nj * 8 + g;
                bf[nj][0] = *(const uint32_t*)(Bs + c0 * TSTR + kb + tg * 2);
                bf[nj][1] = *(const uint32_t*)(Bs + c0 * TSTR + kb + tg * 2 + 8);
            }
            #pragma unroll
            for (int mi = 0; mi < 2; mi++)
                #pragma unroll
                for (int nj = 0; nj < 8; nj++)
                    asm volatile(
                        "mma.sync.aligned.m16n8k16.row.col.f32.bf16.bf16.f32 "
                        "{%0,%1,%2,%3}, {%4,%5,%6,%7}, {%8,%9}, {%0,%1,%2,%3};"
                        : "+f"(acc[mi][nj][0]), "+f"(acc[mi][nj][1]),
                          "+f"(acc[mi][nj][2]), "+f"(acc[mi][nj][3])
                        : "r"(af[mi][0]), "r"(af[mi][1]), "r"(af[mi][2]), "r"(af[mi][3]),
                          "r"(bf[nj][0]), "r"(bf[nj][1]));
        }
        __syncthreads();
        if (has_next) {
            #pragma unroll
            for (int i = 0; i < 2; i++) {
                int r = lr + (i << 6);
                *(uint4*)(As + r * TSTR + lc) = pa[i];
                *(uint4*)(Bs + r * TSTR + lc) = pb[i];
            }
            __syncthreads();
        }
    }

    #pragma unroll
    for (int mi = 0; mi < 2; mi++) {
        #pragma unroll
        for (int nj = 0; nj < 8; nj++) {
            int col = bn + warp_n + nj * 8 + tg * 2;
            size_t r0 = (size_t)(bm + warp_m + mi * 16 + g) * HH + col;
            *(__nv_bfloat162*)(g_cos_h + r0) =
                __float22bfloat162_rn(make_float2(acc[mi][nj][0], acc[mi][nj][1]));
            *(__nv_bfloat162*)(g_cos_h + r0 + 8ULL * HH) =
                __float22bfloat162_rn(make_float2(acc[mi][nj][2], acc[mi][nj][3]));
        }
    }
}

// ---------------- top-96 candidates per row (cached-max argmax) ----------------
__global__ __launch_bounds__(256) void cand_kernel()
{
    const int row = blockIdx.x;
    const int tid = threadIdx.x;
    const __nv_bfloat16* __restrict__ cr = g_cos_h + (size_t)row * HH;

    float v[64];
    #pragma unroll
    for (int i = 0; i < 64; i++) v[i] = __bfloat162float(cr[tid + (i << 8)]);

    unsigned long long removed = 0ULL;
    float bv = -1e30f; int bslot = 0;
    #pragma unroll
    for (int i = 0; i < 64; i++) if (v[i] > bv) { bv = v[i]; bslot = i; }

    __shared__ float wv[8];
    __shared__ int wi[8];
    __shared__ int sfi;

    for (int t = 0; t < CAND; t++) {
        float cv = bv;
        int ci = tid + (bslot << 8);
        #pragma unroll
        for (int off = 16; off; off >>= 1) {
            float ov = __shfl_down_sync(0xffffffffu, cv, off);
            int   oi = __shfl_down_sync(0xffffffffu, ci, off);
            if (ov > cv || (ov == cv && oi < ci)) { cv = ov; ci = oi; }
        }
        if ((tid & 31) == 0) { wv[tid >> 5] = cv; wi[tid >> 5] = ci; }
        __syncthreads();
        if (tid == 0) {
            float fv = wv[0]; int fi = wi[0];
            #pragma unroll
            for (int w = 1; w < 8; w++)
                if (wv[w] > fv || (wv[w] == fv && wi[w] < fi)) { fv = wv[w]; fi = wi[w]; }
            sfi = fi;
            g_cand[(size_t)row * CAND + t] = fi;
        }
        __syncthreads();
        int fi = sfi;
        if (tid == (fi & 255)) {
            removed |= 1ULL << (fi >> 8);
            bv = -1e30f; bslot = 0;
            #pragma unroll
            for (int i = 0; i < 64; i++) {
                bool ok = !((removed >> i) & 1ULL);
                if (ok && v[i] > bv) { bv = v[i]; bslot = i; }
            }
        }
        __syncthreads();
    }
}

// ---------------- rescore: 2-interleaved-accumulator fp32 fma dot ----------------
// s0 accumulates even k, s1 odd k, both ascending, fused fma; total = s0 + s1.
// Activation in bitwise fp32; ranking on fp32 act, ties -> lower index.
__global__ __launch_bounds__(128) void rescore_kernel(float* __restrict__ latent_base)
{
    const int row = blockIdx.x;
    const int tid = threadIdx.x;
    __shared__ float se[DD];
    __shared__ float sact[CAND];
    __shared__ int   sci[CAND];

    #pragma unroll
    for (int i = 0; i < 2; i++)
        ((float4*)se)[tid + i * 128] = ((const float4*)(g_En + (size_t)row * DD))[tid + i * 128];
    __syncthreads();

    if (tid < CAND) {
        const int hidx = g_cand[(size_t)row * CAND + tid];
        const float* __restrict__ w = g_Wn + (size_t)hidx * DD;

        float s0 = 0.0f, s1 = 0.0f;
        for (int i = 0; i < DD / 4; i++) {
            float4 w4 = *(const float4*)(w + i * 4);
            s0 = __fmaf_rn(se[i * 4 + 0], w4.x, s0);
            s1 = __fmaf_rn(se[i * 4 + 1], w4.y, s1);
            s0 = __fmaf_rn(se[i * 4 + 2], w4.z, s0);
            s1 = __fmaf_rn(se[i * 4 + 3], w4.w, s1);
        }
        float s = __fadd_rn(s0, s1);
        float c = fminf(fmaxf(s, -1.0f), 1.0f);
        float t = __fsub_rn(2.0f, __fmul_rn(2.0f, c));
        t = fmaxf(t, 0.0f);
        sact[tid] = __fsub_rn(2.0f, __fsqrt_rn(t));
        sci[tid] = hidx;
    }
    __syncthreads();

    if (tid < CAND) {
        float myv = sact[tid];
        int   myi = sci[tid];
        int rank = 0;
        #pragma unroll 8
        for (int j = 0; j < CAND; j++) {
            float vj = sact[j];
            if (vj > myv || (vj == myv && sci[j] < myi)) rank++;   // tie -> lower idx
        }
        if (rank < TOPK) {
            g_tvals[(size_t)row * TOPK + rank] = myv;
            g_tidx [(size_t)row * TOPK + rank] = myi;
            latent_base[(size_t)row * HH + myi] = myv;
        }
    }
}

// ---------------- sparse decode ----------------
__global__ __launch_bounds__(256) void decode_kernel(const float* __restrict__ vd_b,
                                                     const float* __restrict__ td_b,
                                                     float* __restrict__ out)
{
    const int b = blockIdx.x;
    const int m = blockIdx.y;
    const int tid = threadIdx.x;
    const size_t rowoff = (size_t)m * BB + b;

    __shared__ float sv[TOPK];
    __shared__ int   si[TOPK];
    if (tid < TOPK) {
        sv[tid] = g_tvals[rowoff * TOPK + tid];
        si[tid] = g_tidx [rowoff * TOPK + tid];
    }
    __syncthreads();

    const float* __restrict__ bias = m ? td_b : vd_b;
    const float* __restrict__ Wt = g_WdT + (size_t)m * HH * DD;

    float acc0 = 0.f, acc1 = 0.f, acc2 = 0.f, acc3 = 0.f;
    #pragma unroll 4
    for (int k = 0; k < TOPK; k++) {
        float v = sv[k];
        const float* wr = Wt + (size_t)si[k] * DD;
        acc0 = fmaf(v, wr[tid],       acc0);
        acc1 = fmaf(v, wr[tid + 256], acc1);
        acc2 = fmaf(v, wr[tid + 512], acc2);
        acc3 = fmaf(v, wr[tid + 768], acc3);
    }
    float* orow = out + rowoff * DD;
    orow[tid]       = acc0 + bias[tid];
    orow[tid + 256] = acc1 + bias[tid + 256];
    orow[tid + 512] = acc2 + bias[tid + 512];
    orow[tid + 768] = acc3 + bias[tid + 768];
}

// ---------------- launch ----------------
extern "C" void kernel_launch(void* const* d_in, const int* in_sizes, int n_in,
                              void* d_out, int out_size)
{
    const float* vis  = (const float*)d_in[0];
    const float* txt  = (const float*)d_in[1];
    const float* enc  = (const float*)d_in[2];
    const float* vd_w = (const float*)d_in[3];
    const float* vd_b = (const float*)d_in[4];
    const float* td_w = (const float*)d_in[5];
    const float* td_b = (const float*)d_in[6];

    float* out = (float*)d_out;
    const size_t BD = (size_t)BB * DD;
    const size_t BH = (size_t)BB * HH;
    float* latent_base = out + 2 * BD;

    cudaMemsetAsync(latent_base, 0, 2 * BH * sizeof(float), 0);

    norm_exact_kernel<<<HH, 128>>>(enc, 0);
    norm_exact_kernel<<<BB, 128>>>(vis, 1);
    norm_exact_kernel<<<BB, 128>>>(txt, 2);

    transpose_kernel<<<dim3(HH / 32, DD / 32, 2), dim3(32, 8)>>>(vd_w, td_w);

    gemm_kernel<<<dim3(HH / TBN, ROWS2 / TBM), 256>>>();

    cand_kernel<<<ROWS2, 256>>>();

    rescore_kernel<<<ROWS2, 128>>>(latent_base);

    decode_kernel<<<dim3(BB, 2), 256>>>(vd_b, td_b, out);
}

// round 16
// speedup vs baseline: 1.0507x; 1.0507x over previous
#include <cuda_runtime.h>
#include <cuda_bf16.h>
#include <math.h>
#include <stdint.h>

#define BB 4096
#define DD 1024
#define HH 16384
#define TOPK 32
#define CAND 96
#define ROWS2 (2*BB)

// ---------------- device scratch (allocation-free) ----------------
__device__ float          g_Wn  [(size_t)HH * DD];     // normalized encoder fp32 (exact-rounded)
__device__ __nv_bfloat16  g_Wn_h[(size_t)HH * DD];
__device__ float          g_En  [(size_t)ROWS2 * DD];  // normalized embeddings fp32
__device__ __nv_bfloat16  g_En_h[(size_t)ROWS2 * DD];
__device__ __nv_bfloat16  g_cos_h[(size_t)ROWS2 * HH]; // approx cos (bf16, candidates only)
__device__ float          g_WdT [2ULL * HH * DD];      // transposed decoders [H,D]
__device__ int            g_cand[(size_t)ROWS2 * CAND];
__device__ float          g_tvals[(size_t)ROWS2 * TOPK];
__device__ int            g_tidx [(size_t)ROWS2 * TOPK];

// ---------------- exact normalize: fp64 norm, single fp32 rounding ----------------
__global__ __launch_bounds__(128) void norm_exact_kernel(const float* __restrict__ in, int which)
{
    const int tid = threadIdx.x;
    const int wid = tid >> 5, lane = tid & 31;
    const size_t row = blockIdx.x;

    float* out32;
    __nv_bfloat16* outh;
    if (which == 0) { out32 = g_Wn; outh = g_Wn_h; }
    else {
        out32 = g_En  + (size_t)(which - 1) * BB * DD;
        outh  = g_En_h + (size_t)(which - 1) * BB * DD;
    }

    const float4* ir = (const float4*)(in + row * DD);
    float4 xa = ir[2 * tid];
    float4 xb = ir[2 * tid + 1];

    double s = 0.0;
    s += (double)xa.x * xa.x; s += (double)xa.y * xa.y;
    s += (double)xa.z * xa.z; s += (double)xa.w * xa.w;
    s += (double)xb.x * xb.x; s += (double)xb.y * xb.y;
    s += (double)xb.z * xb.z; s += (double)xb.w * xb.w;

    #pragma unroll
    for (int off = 16; off; off >>= 1)
        s += __shfl_down_sync(0xffffffffu, s, off);

    __shared__ double swarp[4];
    __shared__ double srinv;
    if (lane == 0) swarp[wid] = s;
    __syncthreads();
    if (tid == 0) {
        double tot = swarp[0] + swarp[1] + swarp[2] + swarp[3];
        double n = sqrt(tot);
        if (n < 1e-12) n = 1e-12;
        srinv = 1.0 / n;
    }
    __syncthreads();
    const double r = srinv;

    float4 oa, ob;
    oa.x = (float)((double)xa.x * r); oa.y = (float)((double)xa.y * r);
    oa.z = (float)((double)xa.z * r); oa.w = (float)((double)xa.w * r);
    ob.x = (float)((double)xb.x * r); ob.y = (float)((double)xb.y * r);
    ob.z = (float)((double)xb.z * r); ob.w = (float)((double)xb.w * r);
    ((float4*)(out32 + row * DD))[2 * tid]     = oa;
    ((float4*)(out32 + row * DD))[2 * tid + 1] = ob;
    __nv_bfloat162* oh = (__nv_bfloat162*)(outh + row * DD);
    oh[4 * tid + 0] = __float22bfloat162_rn(make_float2(oa.x, oa.y));
    oh[4 * tid + 1] = __float22bfloat162_rn(make_float2(oa.z, oa.w));
    oh[4 * tid + 2] = __float22bfloat162_rn(make_float2(ob.x, ob.y));
    oh[4 * tid + 3] = __float22bfloat162_rn(make_float2(ob.z, ob.w));
}

// ---------------- decoder transpose [D,H] -> [H,D] ----------------
__global__ __launch_bounds__(256) void transpose_kernel(const float* __restrict__ vdw,
                                                        const float* __restrict__ tdw)
{
    __shared__ float tile[32][33];
    const int m = blockIdx.z;
    const float* in = m ? tdw : vdw;
    float* outp = g_WdT + (size_t)m * HH * DD;
    const int h0 = blockIdx.x * 32;
    const int d0 = blockIdx.y * 32;
    const int tx = threadIdx.x, ty = threadIdx.y;

    #pragma unroll
    for (int r = ty; r < 32; r += 8)
        tile[r][tx] = in[(size_t)(d0 + r) * HH + h0 + tx];
    __syncthreads();
    #pragma unroll
    for (int r = ty; r < 32; r += 8)
        outp[(size_t)(h0 + r) * DD + d0 + tx] = tile[tx][r];
}

// ---------------- bf16 mma.sync GEMM v2: cp.async 3-stage + ldmatrix -------------
#define TBM 128
#define TBN 128
#define TBK 32
#define TSTR 40                          // bf16 elems per smem row (80B, conflict-free)
#define NIT (DD / TBK)                   // 32
#define STAGE_A_BYTES (TBM * TSTR * 2)   // 10240
#define STAGE_BYTES   (2 * STAGE_A_BYTES)
#define GEMM_SMEM     (3 * STAGE_BYTES)  // 61440

__device__ __forceinline__ uint32_t smem_u32g(const void* p) {
    uint32_t a;
    asm("{ .reg .u64 t; cvta.to.shared.u64 t, %1; cvt.u32.u64 %0, t; }" : "=r"(a) : "l"(p));
    return a;
}
__device__ __forceinline__ void cp16(uint32_t dst, const void* src) {
    asm volatile("cp.async.cg.shared.global [%0], [%1], 16;" :: "r"(dst), "l"(src));
}
__device__ __forceinline__ void ldmx4(uint32_t& r0, uint32_t& r1, uint32_t& r2, uint32_t& r3,
                                      uint32_t addr) {
    asm volatile("ldmatrix.sync.aligned.m8n8.x4.shared.b16 {%0,%1,%2,%3}, [%4];"
                 : "=r"(r0), "=r"(r1), "=r"(r2), "=r"(r3) : "r"(addr));
}

__global__ __launch_bounds__(256) void gemm_kernel()
{
    extern __shared__ char smem[];
    const uint32_t sbase = smem_u32g(smem);

    const int tid = threadIdx.x;
    const int wid = tid >> 5, lane = tid & 31;
    const int warp_m = (wid & 3) * 32;
    const int warp_n = (wid >> 2) * 64;
    const int bm = blockIdx.y * TBM;
    const int bn = blockIdx.x * TBN;

    const __nv_bfloat16* __restrict__ gA = g_En_h + (size_t)bm * DD;
    const __nv_bfloat16* __restrict__ gB = g_Wn_h + (size_t)bn * DD;

    // per-thread load assignment: f = tid + i*256, row = f>>2, 16B chunk = f&3
    const int lr0 = tid >> 2, lc0 = (tid & 3);

    // prologue: issue stages 0 and 1
    #pragma unroll
    for (int st = 0; st < 2; st++) {
        const int k0 = st * TBK;
        const uint32_t ab = sbase + st * STAGE_BYTES;
        #pragma unroll
        for (int i = 0; i < 2; i++) {
            int r = lr0 + (i << 6);
            uint32_t off = (uint32_t)r * 80u + (uint32_t)lc0 * 16u;
            cp16(ab + off,                 gA + (size_t)r * DD + k0 + lc0 * 8);
            cp16(ab + STAGE_A_BYTES + off, gB + (size_t)r * DD + k0 + lc0 * 8);
        }
        asm volatile("cp.async.commit_group;");
    }

    float acc[2][8][4];
    #pragma unroll
    for (int mi = 0; mi < 2; mi++)
        #pragma unroll
        for (int nj = 0; nj < 8; nj++)
            #pragma unroll
            for (int q = 0; q < 4; q++) acc[mi][nj][q] = 0.0f;

    const uint32_t lrow = (uint32_t)(lane & 15);
    const uint32_t lcol = (uint32_t)((lane >> 4) << 4);   // +16B for lanes 16-31

    for (int it = 0; it < NIT; it++) {
        if (it == NIT - 1) asm volatile("cp.async.wait_group 0;");
        else               asm volatile("cp.async.wait_group 1;");
        __syncthreads();

        // issue stage it+2 into buffer (it+2)%3 (freed by compute of it-1)
        if (it + 2 < NIT) {
            const int st = (it + 2) % 3;
            const int k0 = (it + 2) * TBK;
            const uint32_t ab = sbase + st * STAGE_BYTES;
            #pragma unroll
            for (int i = 0; i < 2; i++) {
                int r = lr0 + (i << 6);
                uint32_t off = (uint32_t)r * 80u + (uint32_t)lc0 * 16u;
                cp16(ab + off,                 gA + (size_t)r * DD + k0 + lc0 * 8);
                cp16(ab + STAGE_A_BYTES + off, gB + (size_t)r * DD + k0 + lc0 * 8);
            }
        }
        asm volatile("cp.async.commit_group;");

        // compute stage it%3
        const uint32_t abase = sbase + (it % 3) * STAGE_BYTES;
        const uint32_t bbase = abase + STAGE_A_BYTES;

        #pragma unroll
        for (int ks = 0; ks < 2; ks++) {
            const uint32_t kb = (uint32_t)ks * 32u;   // 16 bf16 = 32B
            uint32_t af[2][4], bf[8][2];
            #pragma unroll
            for (int mi = 0; mi < 2; mi++) {
                uint32_t addr = abase + (uint32_t)(warp_m + mi * 16 + lrow) * 80u + kb + lcol;
                ldmx4(af[mi][0], af[mi][1], af[mi][2], af[mi][3], addr);
            }
            #pragma unroll
            for (int ng = 0; ng < 4; ng++) {
                uint32_t r0, r1, r2, r3;
                uint32_t addr = bbase + (uint32_t)(warp_n + ng * 16 + lrow) * 80u + kb + lcol;
                ldmx4(r0, r1, r2, r3, addr);
                bf[ng * 2 + 0][0] = r0; bf[ng * 2 + 0][1] = r2;
                bf[ng * 2 + 1][0] = r1; bf[ng * 2 + 1][1] = r3;
            }
            #pragma unroll
            for (int mi = 0; mi < 2; mi++)
                #pragma unroll
                for (int nj = 0; nj < 8; nj++)
                    asm volatile(
                        "mma.sync.aligned.m16n8k16.row.col.f32.bf16.bf16.f32 "
                        "{%0,%1,%2,%3}, {%4,%5,%6,%7}, {%8,%9}, {%0,%1,%2,%3};"
                        : "+f"(acc[mi][nj][0]), "+f"(acc[mi][nj][1]),
                          "+f"(acc[mi][nj][2]), "+f"(acc[mi][nj][3])
                        : "r"(af[mi][0]), "r"(af[mi][1]), "r"(af[mi][2]), "r"(af[mi][3]),
                          "r"(bf[nj][0]), "r"(bf[nj][1]));
        }
        __syncthreads();
    }

    // epilogue: fp32 accum -> bf16 scores (fragment layout: g=lane>>2, tg=lane&3)
    const int g = lane >> 2, tg = lane & 3;
    #pragma unroll
    for (int mi = 0; mi < 2; mi++) {
        #pragma unroll
        for (int nj = 0; nj < 8; nj++) {
            int col = bn + warp_n + nj * 8 + tg * 2;
            size_t r0 = (size_t)(bm + warp_m + mi * 16 + g) * HH + col;
            *(__nv_bfloat162*)(g_cos_h + r0) =
                __float22bfloat162_rn(make_float2(acc[mi][nj][0], acc[mi][nj][1]));
            *(__nv_bfloat162*)(g_cos_h + r0 + 8ULL * HH) =
                __float22bfloat162_rn(make_float2(acc[mi][nj][2], acc[mi][nj][3]));
        }
    }
}

// ---------------- top-96 candidates per row (cached-max argmax) ----------------
__global__ __launch_bounds__(256) void cand_kernel()
{
    const int row = blockIdx.x;
    const int tid = threadIdx.x;
    const __nv_bfloat16* __restrict__ cr = g_cos_h + (size_t)row * HH;

    float v[64];
    #pragma unroll
    for (int i = 0; i < 64; i++) v[i] = __bfloat162float(cr[tid + (i << 8)]);

    unsigned long long removed = 0ULL;
    float bv = -1e30f; int bslot = 0;
    #pragma unroll
    for (int i = 0; i < 64; i++) if (v[i] > bv) { bv = v[i]; bslot = i; }

    __shared__ float wv[8];
    __shared__ int wi[8];
    __shared__ int sfi;

    for (int t = 0; t < CAND; t++) {
        float cv = bv;
        int ci = tid + (bslot << 8);
        #pragma unroll
        for (int off = 16; off; off >>= 1) {
            float ov = __shfl_down_sync(0xffffffffu, cv, off);
            int   oi = __shfl_down_sync(0xffffffffu, ci, off);
            if (ov > cv || (ov == cv && oi < ci)) { cv = ov; ci = oi; }
        }
        if ((tid & 31) == 0) { wv[tid >> 5] = cv; wi[tid >> 5] = ci; }
        __syncthreads();
        if (tid == 0) {
            float fv = wv[0]; int fi = wi[0];
            #pragma unroll
            for (int w = 1; w < 8; w++)
                if (wv[w] > fv || (wv[w] == fv && wi[w] < fi)) { fv = wv[w]; fi = wi[w]; }
            sfi = fi;
            g_cand[(size_t)row * CAND + t] = fi;
        }
        __syncthreads();
        int fi = sfi;
        if (tid == (fi & 255)) {
            removed |= 1ULL << (fi >> 8);
            bv = -1e30f; bslot = 0;
            #pragma unroll
            for (int i = 0; i < 64; i++) {
                bool ok = !((removed >> i) & 1ULL);
                if (ok && v[i] > bv) { bv = v[i]; bslot = i; }
            }
        }
        __syncthreads();
    }
}

// ---------------- rescore: 2-interleaved-accumulator fp32 fma dot (FROZEN) -------
__global__ __launch_bounds__(128) void rescore_kernel(float* __restrict__ latent_base)
{
    const int row = blockIdx.x;
    const int tid = threadIdx.x;
    __shared__ float se[DD];
    __shared__ float sact[CAND];
    __shared__ int   sci[CAND];

    #pragma unroll
    for (int i = 0; i < 2; i++)
        ((float4*)se)[tid + i * 128] = ((const float4*)(g_En + (size_t)row * DD))[tid + i * 128];
    __syncthreads();

    if (tid < CAND) {
        const int hidx = g_cand[(size_t)row * CAND + tid];
        const float* __restrict__ w = g_Wn + (size_t)hidx * DD;

        float s0 = 0.0f, s1 = 0.0f;
        for (int i = 0; i < DD / 4; i++) {
            float4 w4 = *(const float4*)(w + i * 4);
            s0 = __fmaf_rn(se[i * 4 + 0], w4.x, s0);
            s1 = __fmaf_rn(se[i * 4 + 1], w4.y, s1);
            s0 = __fmaf_rn(se[i * 4 + 2], w4.z, s0);
            s1 = __fmaf_rn(se[i * 4 + 3], w4.w, s1);
        }
        float s = __fadd_rn(s0, s1);
        float c = fminf(fmaxf(s, -1.0f), 1.0f);
        float t = __fsub_rn(2.0f, __fmul_rn(2.0f, c));
        t = fmaxf(t, 0.0f);
        sact[tid] = __fsub_rn(2.0f, __fsqrt_rn(t));
        sci[tid] = hidx;
    }
    __syncthreads();

    if (tid < CAND) {
        float myv = sact[tid];
        int   myi = sci[tid];
        int rank = 0;
        #pragma unroll 8
        for (int j = 0; j < CAND; j++) {
            float vj = sact[j];
            if (vj > myv || (vj == myv && sci[j] < myi)) rank++;   // tie -> lower idx
        }
        if (rank < TOPK) {
            g_tvals[(size_t)row * TOPK + rank] = myv;
            g_tidx [(size_t)row * TOPK + rank] = myi;
            latent_base[(size_t)row * HH + myi] = myv;
        }
    }
}

// ---------------- sparse decode ----------------
__global__ __launch_bounds__(256) void decode_kernel(const float* __restrict__ vd_b,
                                                     const float* __restrict__ td_b,
                                                     float* __restrict__ out)
{
    const int b = blockIdx.x;
    const int m = blockIdx.y;
    const int tid = threadIdx.x;
    const size_t rowoff = (size_t)m * BB + b;

    __shared__ float sv[TOPK];
    __shared__ int   si[TOPK];
    if (tid < TOPK) {
        sv[tid] = g_tvals[rowoff * TOPK + tid];
        si[tid] = g_tidx [rowoff * TOPK + tid];
    }
    __syncthreads();

    const float* __restrict__ bias = m ? td_b : vd_b;
    const float* __restrict__ Wt = g_WdT + (size_t)m * HH * DD;

    float acc0 = 0.f, acc1 = 0.f, acc2 = 0.f, acc3 = 0.f;
    #pragma unroll 4
    for (int k = 0; k < TOPK; k++) {
        float v = sv[k];
        const float* wr = Wt + (size_t)si[k] * DD;
        acc0 = fmaf(v, wr[tid],       acc0);
        acc1 = fmaf(v, wr[tid + 256], acc1);
        acc2 = fmaf(v, wr[tid + 512], acc2);
        acc3 = fmaf(v, wr[tid + 768], acc3);
    }
    float* orow = out + rowoff * DD;
    orow[tid]       = acc0 + bias[tid];
    orow[tid + 256] = acc1 + bias[tid + 256];
    orow[tid + 512] = acc2 + bias[tid + 512];
    orow[tid + 768] = acc3 + bias[tid + 768];
}

// ---------------- launch ----------------
extern "C" void kernel_launch(void* const* d_in, const int* in_sizes, int n_in,
                              void* d_out, int out_size)
{
    const float* vis  = (const float*)d_in[0];
    const float* txt  = (const float*)d_in[1];
    const float* enc  = (const float*)d_in[2];
    const float* vd_w = (const float*)d_in[3];
    const float* vd_b = (const float*)d_in[4];
    const float* td_w = (const float*)d_in[5];
    const float* td_b = (const float*)d_in[6];

    float* out = (float*)d_out;
    const size_t BD = (size_t)BB * DD;
    const size_t BH = (size_t)BB * HH;
    float* latent_base = out + 2 * BD;

    cudaFuncSetAttribute(gemm_kernel, cudaFuncAttributeMaxDynamicSharedMemorySize, GEMM_SMEM);

    cudaMemsetAsync(latent_base, 0, 2 * BH * sizeof(float), 0);

    norm_exact_kernel<<<HH, 128>>>(enc, 0);
    norm_exact_kernel<<<BB, 128>>>(vis, 1);
    norm_exact_kernel<<<BB, 128>>>(txt, 2);

    transpose_kernel<<<dim3(HH / 32, DD / 32, 2), dim3(32, 8)>>>(vd_w, td_w);

    gemm_kernel<<<dim3(HH / TBN, ROWS2 / TBM), 256, GEMM_SMEM>>>();

    cand_kernel<<<ROWS2, 256>>>();

    rescore_kernel<<<ROWS2, 128>>>(latent_base);

    decode_kernel<<<dim3(BB, 2), 256>>>(vd_b, td_b, out);
}